// round 3
// baseline (speedup 1.0000x reference)
#include <cuda_runtime.h>
#include <cstdint>

// FWHT over rows of length 4096: H4096 = H2^{⊗12}.
// 3 register-resident H16 rounds (4 bits each), smem exchanges between them.
// Multi-row CTAs with cp.async double-buffered prefetch keep the DRAM read
// stream continuous across row boundaries.
//
// Bit partition per round:
//   round 1: bits {0,1,10,11}  (from the linear float4 smem read layout)
//   round 2: bits {2,3,4,5}
//   round 3: bits {6,7,8,9}
// XOR swizzle keeps all exchange patterns 32-bank conflict-free.

#define FWHT_N 4096
#define FWHT_THREADS 256
#define ROWS_PER_CTA 8

__device__ __forceinline__ int fwht_swz(int i) {
    // XOR bits {6,7,8} into bits {2,3,4}. Preserves float4 alignment.
    return i ^ (((i >> 6) & 7) << 2);
}

__device__ __forceinline__ void fwht_h16(float* v) {
#pragma unroll
    for (int h = 1; h < 16; h <<= 1) {
#pragma unroll
        for (int s = 0; s < 16; s += 2 * h) {
#pragma unroll
            for (int k = 0; k < h; k++) {
                float a = v[s + k];
                float b = v[s + k + h];
                v[s + k]     = a + b;
                v[s + k + h] = a - b;
            }
        }
    }
}

// Prefetch one full row (16 KB) into a smem buffer: 4 x 16B cp.async per thread.
__device__ __forceinline__ void prefetch_row(float* buf, const float* grow, int t) {
    unsigned int s = (unsigned int)__cvta_generic_to_shared(buf);
#pragma unroll
    for (int j = 0; j < 4; j++) {
        asm volatile("cp.async.cg.shared.global [%0], [%1], 16;\n"
                     :: "r"(s + (unsigned int)(256 * j + t) * 16u),
                        "l"(grow + (size_t)(256 * j + t) * 4));
    }
}

__global__ void __launch_bounds__(FWHT_THREADS)
fwht4096_kernel(const float* __restrict__ x,
                const float* __restrict__ scale,
                float* __restrict__ out,
                int rows)
{
    __shared__ float S[2][FWHT_N];

    const int t = threadIdx.x;
    const long rbeg = (long)blockIdx.x * ROWS_PER_CTA;
    int nr = rows - (int)rbeg;
    if (nr > ROWS_PER_CTA) nr = ROWS_PER_CTA;
    if (nr <= 0) return;

    const float sc = *scale;

    // Prologue: prefetch row 0 into buffer 0.
    prefetch_row(S[0], x + rbeg * FWHT_N, t);
    asm volatile("cp.async.commit_group;\n");

    for (int r = 0; r < nr; r++) {
        float* B = S[r & 1];

        // WAR guard: all threads must be done reading the buffer we are about
        // to prefetch into (it was round-3's read buffer two iterations ago).
        __syncthreads();

        if (r + 1 < nr) {
            prefetch_row(S[(r + 1) & 1], x + (rbeg + r + 1) * (long)FWHT_N, t);
            asm volatile("cp.async.commit_group;\n");
            asm volatile("cp.async.wait_group 1;\n");  // row r's group complete
        } else {
            asm volatile("cp.async.wait_group 0;\n");
        }
        __syncthreads();  // publish row r's data to all threads

        float v[16];

        // ---- round 1: read linear float4 (conflict-free), butterfly bits {0,1,10,11}
#pragma unroll
        for (int j = 0; j < 4; j++) {
            float4 f = *reinterpret_cast<const float4*>(&B[1024 * j + 4 * t]);
            v[4 * j + 0] = f.x;
            v[4 * j + 1] = f.y;
            v[4 * j + 2] = f.z;
            v[4 * j + 3] = f.w;
        }
        fwht_h16(v);

        __syncthreads();  // reads done before swizzled overwrite
#pragma unroll
        for (int j = 0; j < 4; j++) {
            int p = fwht_swz(1024 * j + 4 * t);  // float4-aligned
            *reinterpret_cast<float4*>(&B[p]) =
                make_float4(v[4 * j + 0], v[4 * j + 1], v[4 * j + 2], v[4 * j + 3]);
        }
        __syncthreads();

        // ---- round 2: butterfly bits {2,3,4,5}; per-thread in-place (same addrs)
        {
            const int base = (t & 3) | (((t >> 2) & 7) << 6) | ((t >> 5) << 9);
#pragma unroll
            for (int m = 0; m < 16; m++)
                v[m] = B[fwht_swz(base | (m << 2))];

            fwht_h16(v);

#pragma unroll
            for (int m = 0; m < 16; m++)
                B[fwht_swz(base | (m << 2))] = v[m];
        }
        __syncthreads();

        // ---- round 3: butterfly bits {6,7,8,9}, scale, coalesced stores
        {
            const int base = (t & 63) | ((t >> 6) << 10);
#pragma unroll
            for (int m = 0; m < 16; m++)
                v[m] = B[fwht_swz(base | (m << 6))];

            fwht_h16(v);

            float* orow = out + (rbeg + r) * (long)FWHT_N;
#pragma unroll
            for (int m = 0; m < 16; m++)
                orow[base | (m << 6)] = v[m] * sc;
        }
    }
}

extern "C" void kernel_launch(void* const* d_in, const int* in_sizes, int n_in,
                              void* d_out, int out_size)
{
    const float* x     = (const float*)d_in[0];
    const float* scale = (const float*)d_in[1];
    float* out         = (float*)d_out;

    const int rows = in_sizes[0] / FWHT_N;
    const int grid = (rows + ROWS_PER_CTA - 1) / ROWS_PER_CTA;

    fwht4096_kernel<<<grid, FWHT_THREADS>>>(x, scale, out, rows);
}